// round 12
// baseline (speedup 1.0000x reference)
#include <cuda_runtime.h>
#include <cuda_bf16.h>
#include <cstdint>

// Problem constants
#define B_SZ 8192
#define K_SZ 32
#define D_SZ 512
#define KA   1024            // A cols: [xh | xl] ; Bop K-range: [Mh ; Ml]
#define ASTRIDE 40           // smem row stride in bf16 halves (conflict-free ldmatrix)
#define SA_HALVES (128 * ASTRIDE)
#define NPART 8              // split-K factor for compute_M

// Scratch (device globals — no allocation allowed)
__device__ float  g_c[D_SZ];                          // c = b1 @ w2
__device__ __nv_bfloat16 g_A2[B_SZ * KA];             // 16 MB: [xh | xl]
__device__ __nv_bfloat16 g_Bop[D_SZ * KA];            // 1 MB:  Bop[n][k] = [Mh;Ml] K-major
__device__ float g_MpartT[NPART][D_SZ * D_SZ];        // 8 MB:  partial M, transposed
__device__ float g_qpart[2][B_SZ * D_SZ];             // 32 MB: k-slice partials of q2

__device__ __forceinline__ uint32_t smem_u32(const void* p) {
    uint32_t a;
    asm("{ .reg .u64 t; cvta.to.shared.u64 t, %1; cvt.u32.u64 %0, t; }" : "=r"(a) : "l"(p));
    return a;
}

// ---------------------------------------------------------------------------
// Kernel 1a: split-K partial of M: part[z][n][d] = sum_{e in slice z} w1[e,d]w2[e,n]
// ---------------------------------------------------------------------------
__global__ void compute_M_part_kernel(const float* __restrict__ w1,
                                      const float* __restrict__ w2) {
    __shared__ float As[16][64];
    __shared__ float Bs[16][64];
    const int tid = threadIdx.x;
    const int lRow = tid / 16;
    const int lCol = (tid % 16) * 4;
    const int d0 = blockIdx.y * 64;
    const int j0 = blockIdx.x * 64;
    const int e_lo = blockIdx.z * 64;
    const int tRow = (tid / 16) * 4;
    const int tCol = (tid % 16) * 4;

    float acc[4][4] = {};
    for (int e0 = e_lo; e0 < e_lo + 64; e0 += 16) {
        *(float4*)&As[lRow][lCol] = *(const float4*)(w1 + (e0 + lRow) * D_SZ + d0 + lCol);
        *(float4*)&Bs[lRow][lCol] = *(const float4*)(w2 + (e0 + lRow) * D_SZ + j0 + lCol);
        __syncthreads();
#pragma unroll
        for (int e = 0; e < 16; e++) {
            float rm[4], rn[4];
#pragma unroll
            for (int i = 0; i < 4; i++) rm[i] = As[e][tRow + i];
#pragma unroll
            for (int j = 0; j < 4; j++) rn[j] = Bs[e][tCol + j];
#pragma unroll
            for (int i = 0; i < 4; i++)
#pragma unroll
                for (int j = 0; j < 4; j++)
                    acc[i][j] = fmaf(rm[i], rn[j], acc[i][j]);
        }
        __syncthreads();
    }
    float* part = g_MpartT[blockIdx.z];
#pragma unroll
    for (int jj = 0; jj < 4; jj++) {
        const int n = j0 + tCol + jj;
        float4 v = make_float4(acc[0][jj], acc[1][jj], acc[2][jj], acc[3][jj]);
        *(float4*)(part + (size_t)n * D_SZ + d0 + tRow) = v;
    }
}

// ---------------------------------------------------------------------------
// Kernel 1b: reduce partials, split hi/lo, write g_Bop.
// ---------------------------------------------------------------------------
__global__ void reduce_split_kernel() {
    const int idx = blockIdx.x * blockDim.x + threadIdx.x;  // 65536
    const int n = idx >> 7;
    const int d0 = (idx & 127) * 4;
    float4 s = make_float4(0.f, 0.f, 0.f, 0.f);
#pragma unroll
    for (int p = 0; p < NPART; p++) {
        float4 v = *(const float4*)(g_MpartT[p] + (size_t)n * D_SZ + d0);
        s.x += v.x; s.y += v.y; s.z += v.z; s.w += v.w;
    }
    __nv_bfloat16 h4[4], l4[4];
    const float sv[4] = {s.x, s.y, s.z, s.w};
#pragma unroll
    for (int i = 0; i < 4; i++) {
        __nv_bfloat16 h = __float2bfloat16_rn(sv[i]);
        h4[i] = h;
        l4[i] = __float2bfloat16_rn(sv[i] - __bfloat162float(h));
    }
    *(uint2*)(g_Bop + (size_t)n * KA + d0) = *(uint2*)h4;
    *(uint2*)(g_Bop + (size_t)n * KA + 512 + d0) = *(uint2*)l4;
}

// ---------------------------------------------------------------------------
// Kernel 2: split x -> A2 = [xh | xl]; first 8 CTAs also compute c = b1@w2.
// ---------------------------------------------------------------------------
__global__ void split_x_kernel(const float* __restrict__ x,
                               const float* __restrict__ b1,
                               const float* __restrict__ w2) {
    __shared__ float red[256];
    const int t = blockIdx.x * blockDim.x + threadIdx.x;
    const int b = t >> 7;
    const int c4 = (t & 127) * 4;
    float4 v = *(const float4*)(x + (size_t)b * D_SZ + c4);
    __nv_bfloat16 hx = __float2bfloat16_rn(v.x), hy = __float2bfloat16_rn(v.y);
    __nv_bfloat16 hz = __float2bfloat16_rn(v.z), hw = __float2bfloat16_rn(v.w);
    __nv_bfloat16 lx = __float2bfloat16_rn(v.x - __bfloat162float(hx));
    __nv_bfloat16 ly = __float2bfloat16_rn(v.y - __bfloat162float(hy));
    __nv_bfloat16 lz = __float2bfloat16_rn(v.z - __bfloat162float(hz));
    __nv_bfloat16 lw = __float2bfloat16_rn(v.w - __bfloat162float(hw));
    __nv_bfloat16* row = g_A2 + (size_t)b * KA;
    uint2 hi, lo;
    ((__nv_bfloat16*)&hi)[0] = hx; ((__nv_bfloat16*)&hi)[1] = hy;
    ((__nv_bfloat16*)&hi)[2] = hz; ((__nv_bfloat16*)&hi)[3] = hw;
    ((__nv_bfloat16*)&lo)[0] = lx; ((__nv_bfloat16*)&lo)[1] = ly;
    ((__nv_bfloat16*)&lo)[2] = lz; ((__nv_bfloat16*)&lo)[3] = lw;
    *(uint2*)(row + c4)       = hi;
    *(uint2*)(row + 512 + c4) = lo;

    if (blockIdx.x < 8) {
        const int tid = threadIdx.x;
        const int j = blockIdx.x * 64 + (tid & 63);
        const int eg = tid >> 6;
        float s = 0.f;
        for (int e = eg * 128; e < eg * 128 + 128; e++)
            s = fmaf(b1[e], w2[e * D_SZ + j], s);
        red[tid] = s;
        __syncthreads();
        if (eg == 0)
            g_c[j] = red[tid] + red[tid + 64] + red[tid + 128] + red[tid + 192];
    }
}

// ---------------------------------------------------------------------------
// Kernel 3: warp-MMA bf16 GEMM, always split-K2 (z=blockIdx.z):
//   z=0: k-steps [0,12)   (all dual-B)          -> g_qpart[0]
//   z=1: k-steps [12,32)  (4 dual-B + 16 single)-> g_qpart[1]
// (balanced: 24 MMA-units each). No bias (attn adds it).
// R6-benched mainloop structure (LOAD before wait_group 2).
// ---------------------------------------------------------------------------
__global__ void __launch_bounds__(256, 2)
gemm_mma_kernel(int m_off) {
    extern __shared__ __nv_bfloat16 ds[];
    __nv_bfloat16* sA  = ds;
    __nv_bfloat16* sBh = ds + 3 * SA_HALVES;
    __nv_bfloat16* sBl = ds + 6 * SA_HALVES;

    const int tid = threadIdx.x;
    const int lane = tid & 31;
    const int wid = tid >> 5;
    const int m0 = (blockIdx.y + m_off) * 128;
    const int n0 = blockIdx.x * 128;
    const int mbase = (wid & 3) * 32;
    const int nbase = (wid >> 2) * 64;

    const int z = blockIdx.z;
    const int cBeg = z ? 12 : 0;
    const int cEnd = z ? 32 : 12;
    float* dst = g_qpart[z];

    const __nv_bfloat16* Ab = g_A2 + (size_t)m0 * KA;
    const __nv_bfloat16* Bb = g_Bop + (size_t)n0 * KA;

    const int lrow0 = tid >> 2;
    const int lcc = (tid & 3) * 8;

    const int aRow = mbase + (lane & 15);
    const int aCol = (lane >= 16) ? 8 : 0;
    const int bRow = nbase + ((lane >= 16) ? 8 : 0) + (lane & 7);
    const int bCol = ((lane >> 3) & 1) * 8;

    float acc[2][8][4];
#pragma unroll
    for (int mf = 0; mf < 2; mf++)
#pragma unroll
        for (int nf = 0; nf < 8; nf++)
#pragma unroll
            for (int r = 0; r < 4; r++) acc[mf][nf][r] = 0.f;

#define LOAD_STAGE(buf, c)                                                          \
    do {                                                                            \
        if ((c) < cEnd) {                                                           \
            const int kb = ((c) & 15) * 32;                                         \
            _Pragma("unroll")                                                       \
            for (int i = 0; i < 2; i++) {                                           \
                int row = lrow0 + i * 64;                                           \
                uint32_t da = smem_u32(&sA[(buf) * SA_HALVES + row * ASTRIDE + lcc]); \
                const void* pa = Ab + (size_t)row * KA + (c) * 32 + lcc;            \
                asm volatile("cp.async.cg.shared.global [%0], [%1], 16;"            \
                             :: "r"(da), "l"(pa) : "memory");                       \
                uint32_t dh = smem_u32(&sBh[(buf) * SA_HALVES + row * ASTRIDE + lcc]); \
                const void* ph = Bb + (size_t)row * KA + kb + lcc;                  \
                asm volatile("cp.async.cg.shared.global [%0], [%1], 16;"            \
                             :: "r"(dh), "l"(ph) : "memory");                       \
                if ((c) < 16) {                                                     \
                    uint32_t dl = smem_u32(&sBl[(buf) * SA_HALVES + row * ASTRIDE + lcc]); \
                    const void* pl = Bb + (size_t)row * KA + 512 + kb + lcc;        \
                    asm volatile("cp.async.cg.shared.global [%0], [%1], 16;"        \
                                 :: "r"(dl), "l"(pl) : "memory");                   \
                }                                                                   \
            }                                                                       \
        }                                                                           \
        asm volatile("cp.async.commit_group;" ::: "memory");                        \
    } while (0)

    LOAD_STAGE(0, cBeg);
    LOAD_STAGE(1, cBeg + 1);

    int buf = 0, nbuf2 = 2;
    for (int c = cBeg; c < cEnd; ++c) {
        LOAD_STAGE(nbuf2, c + 2);
        asm volatile("cp.async.wait_group 2;" ::: "memory");
        __syncthreads();

#pragma unroll
        for (int kf = 0; kf < 2; kf++) {
            uint32_t a[2][4];
#pragma unroll
            for (int mf = 0; mf < 2; mf++) {
                uint32_t addr = smem_u32(
                    &sA[buf * SA_HALVES + (aRow + mf * 16) * ASTRIDE + kf * 16 + aCol]);
                asm volatile(
                    "ldmatrix.sync.aligned.m8n8.x4.shared.b16 {%0,%1,%2,%3}, [%4];"
                    : "=r"(a[mf][0]), "=r"(a[mf][1]), "=r"(a[mf][2]), "=r"(a[mf][3])
                    : "r"(addr));
            }
            uint32_t b[4][4];
#pragma unroll
            for (int np = 0; np < 4; np++) {
                uint32_t addr = smem_u32(
                    &sBh[buf * SA_HALVES + (bRow + np * 16) * ASTRIDE + kf * 16 + bCol]);
                asm volatile(
                    "ldmatrix.sync.aligned.m8n8.x4.shared.b16 {%0,%1,%2,%3}, [%4];"
                    : "=r"(b[np][0]), "=r"(b[np][1]), "=r"(b[np][2]), "=r"(b[np][3])
                    : "r"(addr));
            }
#pragma unroll
            for (int mf = 0; mf < 2; mf++)
#pragma unroll
                for (int nf = 0; nf < 8; nf++) {
                    asm volatile(
                        "mma.sync.aligned.m16n8k16.row.col.f32.bf16.bf16.f32 "
                        "{%0,%1,%2,%3}, {%4,%5,%6,%7}, {%8,%9}, {%0,%1,%2,%3};"
                        : "+f"(acc[mf][nf][0]), "+f"(acc[mf][nf][1]),
                          "+f"(acc[mf][nf][2]), "+f"(acc[mf][nf][3])
                        : "r"(a[mf][0]), "r"(a[mf][1]), "r"(a[mf][2]), "r"(a[mf][3]),
                          "r"(b[nf >> 1][(nf & 1) * 2]), "r"(b[nf >> 1][(nf & 1) * 2 + 1]));
                }
            if (c < 16) {
#pragma unroll
                for (int np = 0; np < 4; np++) {
                    uint32_t addr = smem_u32(
                        &sBl[buf * SA_HALVES + (bRow + np * 16) * ASTRIDE + kf * 16 + bCol]);
                    asm volatile(
                        "ldmatrix.sync.aligned.m8n8.x4.shared.b16 {%0,%1,%2,%3}, [%4];"
                        : "=r"(b[np][0]), "=r"(b[np][1]), "=r"(b[np][2]), "=r"(b[np][3])
                        : "r"(addr));
                }
#pragma unroll
                for (int mf = 0; mf < 2; mf++)
#pragma unroll
                    for (int nf = 0; nf < 8; nf++) {
                        asm volatile(
                            "mma.sync.aligned.m16n8k16.row.col.f32.bf16.bf16.f32 "
                            "{%0,%1,%2,%3}, {%4,%5,%6,%7}, {%8,%9}, {%0,%1,%2,%3};"
                            : "+f"(acc[mf][nf][0]), "+f"(acc[mf][nf][1]),
                              "+f"(acc[mf][nf][2]), "+f"(acc[mf][nf][3])
                            : "r"(a[mf][0]), "r"(a[mf][1]), "r"(a[mf][2]), "r"(a[mf][3]),
                              "r"(b[nf >> 1][(nf & 1) * 2]), "r"(b[nf >> 1][(nf & 1) * 2 + 1]));
                    }
            }
        }
        __syncthreads();
        buf = (buf == 2) ? 0 : buf + 1;
        nbuf2 = (nbuf2 == 2) ? 0 : nbuf2 + 1;
    }

    // Epilogue: raw partial -> g_qpart[z] (no bias; attn adds it)
    const int g = lane >> 2;
    const int t4 = lane & 3;
#pragma unroll
    for (int mf = 0; mf < 2; mf++) {
#pragma unroll
        for (int nf = 0; nf < 8; nf++) {
            const int col = n0 + nbase + nf * 8 + t4 * 2;
            const int r0 = m0 + mbase + mf * 16 + g;
            float2 v0 = make_float2(acc[mf][nf][0], acc[mf][nf][1]);
            float2 v1 = make_float2(acc[mf][nf][2], acc[mf][nf][3]);
            *(float2*)(dst + (size_t)r0 * D_SZ + col) = v0;
            *(float2*)(dst + (size_t)(r0 + 8) * D_SZ + col) = v1;
        }
    }
}

// ---------------------------------------------------------------------------
// Kernel 4: attention; q2 row = qpart0 + qpart1 + bias (summed on load).
// ---------------------------------------------------------------------------
__global__ void __launch_bounds__(256)
attn_kernel(const float* __restrict__ x,
            const float* __restrict__ keys,
            const float* __restrict__ values,
            float* __restrict__ out, int b_off) {
    const int b = blockIdx.x + b_off;
    const int tid = threadIdx.x;
    const int lane = tid & 31;
    const int warp = tid >> 5;

    __shared__ float4 q2s[128];
    __shared__ float sc[32];
    __shared__ float attn_s[32];

    if (tid < 128) {
        float4 p0 = ((const float4*)g_qpart[0])[(size_t)b * 128 + tid];
        float4 p1 = ((const float4*)g_qpart[1])[(size_t)b * 128 + tid];
        float4 cb = ((const float4*)g_c)[tid];
        q2s[tid] = make_float4(p0.x + p1.x + cb.x, p0.y + p1.y + cb.y,
                               p0.z + p1.z + cb.z, p0.w + p1.w + cb.w);
    }
    __syncthreads();

    const float4* K4 = (const float4*)keys;
#pragma unroll
    for (int kk = 0; kk < 4; kk++) {
        const int k = warp * 4 + kk;
        const long base = ((long)b * K_SZ + k) * 128;
        float s = 0.f;
#pragma unroll
        for (int i = 0; i < 4; i++) {
            float4 kv = K4[base + i * 32 + lane];
            float4 qv = q2s[i * 32 + lane];
            s = fmaf(kv.x, qv.x, s);
            s = fmaf(kv.y, qv.y, s);
            s = fmaf(kv.z, qv.z, s);
            s = fmaf(kv.w, qv.w, s);
        }
#pragma unroll
        for (int off = 16; off; off >>= 1)
            s += __shfl_xor_sync(0xffffffffu, s, off);
        if (lane == 0) sc[k] = s * 0.044194173824159216f;  // 1/sqrt(512)
    }
    __syncthreads();

    if (tid < 32) {
        float s = sc[tid];
        float m = s;
#pragma unroll
        for (int off = 16; off; off >>= 1)
            m = fmaxf(m, __shfl_xor_sync(0xffffffffu, m, off));
        float p = __expf(s - m);
        float sum = p;
#pragma unroll
        for (int off = 16; off; off >>= 1)
            sum += __shfl_xor_sync(0xffffffffu, sum, off);
        attn_s[tid] = p / sum;
    }
    __syncthreads();

    const float2* V2 = (const float2*)values;
    const float2* X2 = (const float2*)x;
    float2 acc = make_float2(0.f, 0.f);
    const long vbase = (long)b * K_SZ * 256;
#pragma unroll
    for (int k = 0; k < K_SZ; k++) {
        const float a = attn_s[k];
        float2 v = V2[vbase + k * 256 + tid];
        acc.x = fmaf(a, v.x, acc.x);
        acc.y = fmaf(a, v.y, acc.y);
    }
    float2 xv = X2[(long)b * 256 + tid];
    float2 o;
    o.x = 0.5f * xv.x + 0.5f * acc.x;
    o.y = 0.5f * xv.y + 0.5f * acc.y;
    ((float2*)out)[(long)b * 256 + tid] = o;
}

// ---------------------------------------------------------------------------
extern "C" void kernel_launch(void* const* d_in, const int* in_sizes, int n_in,
                              void* d_out, int out_size) {
    (void)in_sizes; (void)n_in; (void)out_size;
    const float* x      = (const float*)d_in[0];
    const float* keys   = (const float*)d_in[1];
    const float* values = (const float*)d_in[2];
    const float* w1     = (const float*)d_in[3];
    const float* b1     = (const float*)d_in[4];
    const float* w2     = (const float*)d_in[5];
    // d_in[6] = b2: per-row constant in scores -> cancels in softmax.
    float* out = (float*)d_out;

    static cudaStream_t s2 = nullptr, s3 = nullptr;
    static cudaEvent_t evRoot = nullptr, evSplit = nullptr, evRS = nullptr,
                       ev1 = nullptr, ev2 = nullptr, ev3 = nullptr, ev4 = nullptr,
                       evJoin = nullptr, evJoin3 = nullptr;
    if (!s2) {
        cudaStreamCreateWithFlags(&s2, cudaStreamNonBlocking);
        cudaStreamCreateWithFlags(&s3, cudaStreamNonBlocking);
        cudaEventCreateWithFlags(&evRoot, cudaEventDisableTiming);
        cudaEventCreateWithFlags(&evSplit, cudaEventDisableTiming);
        cudaEventCreateWithFlags(&evRS, cudaEventDisableTiming);
        cudaEventCreateWithFlags(&ev1, cudaEventDisableTiming);
        cudaEventCreateWithFlags(&ev2, cudaEventDisableTiming);
        cudaEventCreateWithFlags(&ev3, cudaEventDisableTiming);
        cudaEventCreateWithFlags(&ev4, cudaEventDisableTiming);
        cudaEventCreateWithFlags(&evJoin, cudaEventDisableTiming);
        cudaEventCreateWithFlags(&evJoin3, cudaEventDisableTiming);
    }

    const int gemm_smem = 9 * SA_HALVES * (int)sizeof(__nv_bfloat16);  // 92160
    cudaFuncSetAttribute(gemm_mma_kernel,
                         cudaFuncAttributeMaxDynamicSharedMemorySize, gemm_smem);

    // Fork s2 off the main (captured) stream.
    cudaEventRecord(evRoot, 0);
    cudaStreamWaitEvent(s2, evRoot, 0);
    cudaStreamWaitEvent(s3, evRoot, 0);

    // s2: split_x (independent of the M-chain)
    split_x_kernel<<<4096, 256, 0, s2>>>(x, b1, w2);
    cudaEventRecord(evSplit, s2);

    // main: M-chain
    compute_M_part_kernel<<<dim3(8, 8, 8), 256>>>(w1, w2);
    reduce_split_kernel<<<256, 256>>>();
    cudaEventRecord(evRS, 0);

    // main stream: g1 (rows 0..1023), then g3 (rows 3072..5119)
    cudaStreamWaitEvent(0, evSplit, 0);
    gemm_mma_kernel<<<dim3(4, 8, 2), 256, gemm_smem>>>(0);
    cudaEventRecord(ev1, 0);
    gemm_mma_kernel<<<dim3(4, 16, 2), 256, gemm_smem>>>(24);
    cudaEventRecord(ev3, 0);

    // s3: g2 (rows 1024..3071), then g4 (rows 5120..8191) — concurrent with main
    cudaStreamWaitEvent(s3, evSplit, 0);
    cudaStreamWaitEvent(s3, evRS, 0);
    gemm_mma_kernel<<<dim3(4, 16, 2), 256, gemm_smem, s3>>>(8);
    cudaEventRecord(ev2, s3);
    gemm_mma_kernel<<<dim3(4, 24, 2), 256, gemm_smem, s3>>>(40);
    cudaEventRecord(ev4, s3);

    // s2: attention chunks, gated on gemm events
    cudaStreamWaitEvent(s2, ev1, 0);
    attn_kernel<<<1024, 256, 0, s2>>>(x, keys, values, out, 0);
    cudaStreamWaitEvent(s2, ev2, 0);
    attn_kernel<<<2048, 256, 0, s2>>>(x, keys, values, out, 1024);
    cudaStreamWaitEvent(s2, ev3, 0);
    attn_kernel<<<2048, 256, 0, s2>>>(x, keys, values, out, 3072);
    cudaStreamWaitEvent(s2, ev4, 0);
    attn_kernel<<<3072, 256, 0, s2>>>(x, keys, values, out, 5120);

    // Join s2 and s3 back into the captured stream.
    cudaEventRecord(evJoin, s2);
    cudaStreamWaitEvent(0, evJoin, 0);
    cudaEventRecord(evJoin3, s3);
    cudaStreamWaitEvent(0, evJoin3, 0);
}

// round 14
// speedup vs baseline: 1.0827x; 1.0827x over previous
#include <cuda_runtime.h>
#include <cuda_bf16.h>
#include <cstdint>

// Problem constants
#define B_SZ 8192
#define K_SZ 32
#define D_SZ 512
#define KA   1024            // A cols: [xh | xl] ; Bop K-range: [Mh ; Ml]
#define ASTRIDE 40           // smem row stride in bf16 halves (conflict-free ldmatrix)
#define SA_HALVES (128 * ASTRIDE)
#define NPART 8              // split-K factor for compute_M
#define Q1ROWS 2048          // rows computed by the split-K lead chunk

// Scratch (device globals — no allocation allowed)
__device__ float4 g_q2[B_SZ * (D_SZ / 4)];            // 16 MB: q2 = x@M + c
__device__ float  g_c[D_SZ];                          // c = b1 @ w2
__device__ __nv_bfloat16 g_A2[B_SZ * KA];             // 16 MB: [xh | xl]
__device__ __nv_bfloat16 g_Bop[D_SZ * KA];            // 1 MB:  Bop[n][k] = [Mh;Ml] K-major
__device__ float g_MpartT[NPART][D_SZ * D_SZ];        // 8 MB:  partial M, transposed
__device__ float g_qpart[4][Q1ROWS * D_SZ];           // 16 MB: split-K partials, rows 0..2047

__device__ __forceinline__ uint32_t smem_u32(const void* p) {
    uint32_t a;
    asm("{ .reg .u64 t; cvta.to.shared.u64 t, %1; cvt.u32.u64 %0, t; }" : "=r"(a) : "l"(p));
    return a;
}

// ---------------------------------------------------------------------------
// Kernel 1a: split-K partial of M: part[z][n][d] = sum_{e in slice z} w1[e,d]w2[e,n]
// ---------------------------------------------------------------------------
__global__ void compute_M_part_kernel(const float* __restrict__ w1,
                                      const float* __restrict__ w2) {
    __shared__ float As[16][64];
    __shared__ float Bs[16][64];
    const int tid = threadIdx.x;
    const int lRow = tid / 16;
    const int lCol = (tid % 16) * 4;
    const int d0 = blockIdx.y * 64;
    const int j0 = blockIdx.x * 64;
    const int e_lo = blockIdx.z * 64;
    const int tRow = (tid / 16) * 4;
    const int tCol = (tid % 16) * 4;

    float acc[4][4] = {};
    for (int e0 = e_lo; e0 < e_lo + 64; e0 += 16) {
        *(float4*)&As[lRow][lCol] = *(const float4*)(w1 + (e0 + lRow) * D_SZ + d0 + lCol);
        *(float4*)&Bs[lRow][lCol] = *(const float4*)(w2 + (e0 + lRow) * D_SZ + j0 + lCol);
        __syncthreads();
#pragma unroll
        for (int e = 0; e < 16; e++) {
            float rm[4], rn[4];
#pragma unroll
            for (int i = 0; i < 4; i++) rm[i] = As[e][tRow + i];
#pragma unroll
            for (int j = 0; j < 4; j++) rn[j] = Bs[e][tCol + j];
#pragma unroll
            for (int i = 0; i < 4; i++)
#pragma unroll
                for (int j = 0; j < 4; j++)
                    acc[i][j] = fmaf(rm[i], rn[j], acc[i][j]);
        }
        __syncthreads();
    }
    float* part = g_MpartT[blockIdx.z];
#pragma unroll
    for (int jj = 0; jj < 4; jj++) {
        const int n = j0 + tCol + jj;
        float4 v = make_float4(acc[0][jj], acc[1][jj], acc[2][jj], acc[3][jj]);
        *(float4*)(part + (size_t)n * D_SZ + d0 + tRow) = v;
    }
}

// ---------------------------------------------------------------------------
// Kernel 1b: reduce partials, split hi/lo, write g_Bop.
// ---------------------------------------------------------------------------
__global__ void reduce_split_kernel() {
    const int idx = blockIdx.x * blockDim.x + threadIdx.x;  // 65536
    const int n = idx >> 7;
    const int d0 = (idx & 127) * 4;
    float4 s = make_float4(0.f, 0.f, 0.f, 0.f);
#pragma unroll
    for (int p = 0; p < NPART; p++) {
        float4 v = *(const float4*)(g_MpartT[p] + (size_t)n * D_SZ + d0);
        s.x += v.x; s.y += v.y; s.z += v.z; s.w += v.w;
    }
    __nv_bfloat16 h4[4], l4[4];
    const float sv[4] = {s.x, s.y, s.z, s.w};
#pragma unroll
    for (int i = 0; i < 4; i++) {
        __nv_bfloat16 h = __float2bfloat16_rn(sv[i]);
        h4[i] = h;
        l4[i] = __float2bfloat16_rn(sv[i] - __bfloat162float(h));
    }
    *(uint2*)(g_Bop + (size_t)n * KA + d0) = *(uint2*)h4;
    *(uint2*)(g_Bop + (size_t)n * KA + 512 + d0) = *(uint2*)l4;
}

// ---------------------------------------------------------------------------
// Kernel 2: split x -> A2 = [xh | xl]; first 8 CTAs also compute c = b1@w2.
// ---------------------------------------------------------------------------
__global__ void split_x_kernel(const float* __restrict__ x,
                               const float* __restrict__ b1,
                               const float* __restrict__ w2) {
    __shared__ float red[256];
    const int t = blockIdx.x * blockDim.x + threadIdx.x;
    const int b = t >> 7;
    const int c4 = (t & 127) * 4;
    float4 v = *(const float4*)(x + (size_t)b * D_SZ + c4);
    __nv_bfloat16 hx = __float2bfloat16_rn(v.x), hy = __float2bfloat16_rn(v.y);
    __nv_bfloat16 hz = __float2bfloat16_rn(v.z), hw = __float2bfloat16_rn(v.w);
    __nv_bfloat16 lx = __float2bfloat16_rn(v.x - __bfloat162float(hx));
    __nv_bfloat16 ly = __float2bfloat16_rn(v.y - __bfloat162float(hy));
    __nv_bfloat16 lz = __float2bfloat16_rn(v.z - __bfloat162float(hz));
    __nv_bfloat16 lw = __float2bfloat16_rn(v.w - __bfloat162float(hw));
    __nv_bfloat16* row = g_A2 + (size_t)b * KA;
    uint2 hi, lo;
    ((__nv_bfloat16*)&hi)[0] = hx; ((__nv_bfloat16*)&hi)[1] = hy;
    ((__nv_bfloat16*)&hi)[2] = hz; ((__nv_bfloat16*)&hi)[3] = hw;
    ((__nv_bfloat16*)&lo)[0] = lx; ((__nv_bfloat16*)&lo)[1] = ly;
    ((__nv_bfloat16*)&lo)[2] = lz; ((__nv_bfloat16*)&lo)[3] = lw;
    *(uint2*)(row + c4)       = hi;
    *(uint2*)(row + 512 + c4) = lo;

    if (blockIdx.x < 8) {
        const int tid = threadIdx.x;
        const int j = blockIdx.x * 64 + (tid & 63);
        const int eg = tid >> 6;
        float s = 0.f;
        for (int e = eg * 128; e < eg * 128 + 128; e++)
            s = fmaf(b1[e], w2[e * D_SZ + j], s);
        red[tid] = s;
        __syncthreads();
        if (eg == 0)
            g_c[j] = red[tid] + red[tid + 64] + red[tid + 128] + red[tid + 192];
    }
}

// ---------------------------------------------------------------------------
// Kernel 3: warp-MMA bf16 GEMM: q2 = xh@Mh + xh@Ml + xl@Mh (+ c if !kspl)
// R6-benched mainloop. kspl=1: blockIdx.z selects k-slice [z*8, z*8+8),
// raw partials -> g_qpart[z]. kspl=0: full k, bias added, -> g_q2.
// ---------------------------------------------------------------------------
__global__ void __launch_bounds__(256, 2)
gemm_mma_kernel(int m_off, int kspl) {
    extern __shared__ __nv_bfloat16 ds[];
    __nv_bfloat16* sA  = ds;
    __nv_bfloat16* sBh = ds + 3 * SA_HALVES;
    __nv_bfloat16* sBl = ds + 6 * SA_HALVES;

    const int tid = threadIdx.x;
    const int lane = tid & 31;
    const int wid = tid >> 5;
    const int m0 = (blockIdx.y + m_off) * 128;
    const int n0 = blockIdx.x * 128;
    const int mbase = (wid & 3) * 32;
    const int nbase = (wid >> 2) * 64;

    int cBeg = 0, cEnd = 32;
    float* dst = (float*)g_q2;
    if (kspl) {
        const int z = blockIdx.z;
        cBeg = z * 8;
        cEnd = cBeg + 8;
        dst = g_qpart[z];
    }

    const __nv_bfloat16* Ab = g_A2 + (size_t)m0 * KA;
    const __nv_bfloat16* Bb = g_Bop + (size_t)n0 * KA;

    const int lrow0 = tid >> 2;
    const int lcc = (tid & 3) * 8;

    const int aRow = mbase + (lane & 15);
    const int aCol = (lane >= 16) ? 8 : 0;
    const int bRow = nbase + ((lane >= 16) ? 8 : 0) + (lane & 7);
    const int bCol = ((lane >> 3) & 1) * 8;

    float acc[2][8][4];
#pragma unroll
    for (int mf = 0; mf < 2; mf++)
#pragma unroll
        for (int nf = 0; nf < 8; nf++)
#pragma unroll
            for (int r = 0; r < 4; r++) acc[mf][nf][r] = 0.f;

#define LOAD_STAGE(buf, c)                                                          \
    do {                                                                            \
        if ((c) < cEnd) {                                                           \
            const int kb = ((c) & 15) * 32;                                         \
            _Pragma("unroll")                                                       \
            for (int i = 0; i < 2; i++) {                                           \
                int row = lrow0 + i * 64;                                           \
                uint32_t da = smem_u32(&sA[(buf) * SA_HALVES + row * ASTRIDE + lcc]); \
                const void* pa = Ab + (size_t)row * KA + (c) * 32 + lcc;            \
                asm volatile("cp.async.cg.shared.global [%0], [%1], 16;"            \
                             :: "r"(da), "l"(pa) : "memory");                       \
                uint32_t dh = smem_u32(&sBh[(buf) * SA_HALVES + row * ASTRIDE + lcc]); \
                const void* ph = Bb + (size_t)row * KA + kb + lcc;                  \
                asm volatile("cp.async.cg.shared.global [%0], [%1], 16;"            \
                             :: "r"(dh), "l"(ph) : "memory");                       \
                if ((c) < 16) {                                                     \
                    uint32_t dl = smem_u32(&sBl[(buf) * SA_HALVES + row * ASTRIDE + lcc]); \
                    const void* pl = Bb + (size_t)row * KA + 512 + kb + lcc;        \
                    asm volatile("cp.async.cg.shared.global [%0], [%1], 16;"        \
                                 :: "r"(dl), "l"(pl) : "memory");                   \
                }                                                                   \
            }                                                                       \
        }                                                                           \
        asm volatile("cp.async.commit_group;" ::: "memory");                        \
    } while (0)

    LOAD_STAGE(0, cBeg);
    LOAD_STAGE(1, cBeg + 1);

    int buf = 0, nbuf2 = 2;
    for (int c = cBeg; c < cEnd; ++c) {
        LOAD_STAGE(nbuf2, c + 2);
        asm volatile("cp.async.wait_group 2;" ::: "memory");
        __syncthreads();

#pragma unroll
        for (int kf = 0; kf < 2; kf++) {
            uint32_t a[2][4];
#pragma unroll
            for (int mf = 0; mf < 2; mf++) {
                uint32_t addr = smem_u32(
                    &sA[buf * SA_HALVES + (aRow + mf * 16) * ASTRIDE + kf * 16 + aCol]);
                asm volatile(
                    "ldmatrix.sync.aligned.m8n8.x4.shared.b16 {%0,%1,%2,%3}, [%4];"
                    : "=r"(a[mf][0]), "=r"(a[mf][1]), "=r"(a[mf][2]), "=r"(a[mf][3])
                    : "r"(addr));
            }
            uint32_t b[4][4];
#pragma unroll
            for (int np = 0; np < 4; np++) {
                uint32_t addr = smem_u32(
                    &sBh[buf * SA_HALVES + (bRow + np * 16) * ASTRIDE + kf * 16 + bCol]);
                asm volatile(
                    "ldmatrix.sync.aligned.m8n8.x4.shared.b16 {%0,%1,%2,%3}, [%4];"
                    : "=r"(b[np][0]), "=r"(b[np][1]), "=r"(b[np][2]), "=r"(b[np][3])
                    : "r"(addr));
            }
#pragma unroll
            for (int mf = 0; mf < 2; mf++)
#pragma unroll
                for (int nf = 0; nf < 8; nf++) {
                    asm volatile(
                        "mma.sync.aligned.m16n8k16.row.col.f32.bf16.bf16.f32 "
                        "{%0,%1,%2,%3}, {%4,%5,%6,%7}, {%8,%9}, {%0,%1,%2,%3};"
                        : "+f"(acc[mf][nf][0]), "+f"(acc[mf][nf][1]),
                          "+f"(acc[mf][nf][2]), "+f"(acc[mf][nf][3])
                        : "r"(a[mf][0]), "r"(a[mf][1]), "r"(a[mf][2]), "r"(a[mf][3]),
                          "r"(b[nf >> 1][(nf & 1) * 2]), "r"(b[nf >> 1][(nf & 1) * 2 + 1]));
                }
            if (c < 16) {
#pragma unroll
                for (int np = 0; np < 4; np++) {
                    uint32_t addr = smem_u32(
                        &sBl[buf * SA_HALVES + (bRow + np * 16) * ASTRIDE + kf * 16 + bCol]);
                    asm volatile(
                        "ldmatrix.sync.aligned.m8n8.x4.shared.b16 {%0,%1,%2,%3}, [%4];"
                        : "=r"(b[np][0]), "=r"(b[np][1]), "=r"(b[np][2]), "=r"(b[np][3])
                        : "r"(addr));
                }
#pragma unroll
                for (int mf = 0; mf < 2; mf++)
#pragma unroll
                    for (int nf = 0; nf < 8; nf++) {
                        asm volatile(
                            "mma.sync.aligned.m16n8k16.row.col.f32.bf16.bf16.f32 "
                            "{%0,%1,%2,%3}, {%4,%5,%6,%7}, {%8,%9}, {%0,%1,%2,%3};"
                            : "+f"(acc[mf][nf][0]), "+f"(acc[mf][nf][1]),
                              "+f"(acc[mf][nf][2]), "+f"(acc[mf][nf][3])
                            : "r"(a[mf][0]), "r"(a[mf][1]), "r"(a[mf][2]), "r"(a[mf][3]),
                              "r"(b[nf >> 1][(nf & 1) * 2]), "r"(b[nf >> 1][(nf & 1) * 2 + 1]));
                    }
            }
        }
        __syncthreads();
        buf = (buf == 2) ? 0 : buf + 1;
        nbuf2 = (nbuf2 == 2) ? 0 : nbuf2 + 1;
    }

    // Epilogue (bias only for the full-k path)
    const float bmul = kspl ? 0.f : 1.f;
    const int g = lane >> 2;
    const int t4 = lane & 3;
#pragma unroll
    for (int mf = 0; mf < 2; mf++) {
#pragma unroll
        for (int nf = 0; nf < 8; nf++) {
            const int col = n0 + nbase + nf * 8 + t4 * 2;
            const float c0 = g_c[col] * bmul, c1 = g_c[col + 1] * bmul;
            const int r0 = m0 + mbase + mf * 16 + g;
            float2 v0 = make_float2(acc[mf][nf][0] + c0, acc[mf][nf][1] + c1);
            float2 v1 = make_float2(acc[mf][nf][2] + c0, acc[mf][nf][3] + c1);
            *(float2*)(dst + (size_t)r0 * D_SZ + col) = v0;
            *(float2*)(dst + (size_t)(r0 + 8) * D_SZ + col) = v1;
        }
    }
}

// ---------------------------------------------------------------------------
// Kernel 4: attention, 2 rows per CTA. use_part=1: q2 row = sum of 4 k-slice
// partials + bias (lead rows); use_part=0: read g_q2 directly.
// ---------------------------------------------------------------------------
__global__ void __launch_bounds__(256)
attn_kernel(const float* __restrict__ x,
            const float* __restrict__ keys,
            const float* __restrict__ values,
            float* __restrict__ out, int b_off, int use_part) {
    const int b0 = (blockIdx.x << 1) + b_off;
    const int tid = threadIdx.x;
    const int lane = tid & 31;
    const int warp = tid >> 5;

    __shared__ float4 q2s[2][128];
    __shared__ float sc[2][32];
    __shared__ float attn_s[2][32];

    // Load 2 q2 rows (256 threads: row = tid>>7, idx = tid&127)
    {
        const int row = tid >> 7, idx = tid & 127;
        const size_t gq = (size_t)(b0 + row) * 128 + idx;
        float4 q;
        if (use_part) {
            float4 p0 = ((const float4*)g_qpart[0])[gq];
            float4 p1 = ((const float4*)g_qpart[1])[gq];
            float4 p2 = ((const float4*)g_qpart[2])[gq];
            float4 p3 = ((const float4*)g_qpart[3])[gq];
            float4 cb = ((const float4*)g_c)[idx];
            q = make_float4(p0.x + p1.x + p2.x + p3.x + cb.x,
                            p0.y + p1.y + p2.y + p3.y + cb.y,
                            p0.z + p1.z + p2.z + p3.z + cb.z,
                            p0.w + p1.w + p2.w + p3.w + cb.w);
        } else {
            q = g_q2[gq];
        }
        q2s[row][idx] = q;
    }
    __syncthreads();

    // Scores: warp w -> row = w>>2, k-group = w&3 (8 k's per warp)
    {
        const int row = warp >> 2, kg = warp & 3;
        const int b = b0 + row;
        const float4* K4 = (const float4*)keys;
#pragma unroll
        for (int kk = 0; kk < 8; kk++) {
            const int k = kg * 8 + kk;
            const size_t base = ((size_t)b * K_SZ + k) * 128;
            float s = 0.f;
#pragma unroll
            for (int i = 0; i < 4; i++) {
                float4 kv = K4[base + i * 32 + lane];
                float4 qv = q2s[row][i * 32 + lane];
                s = fmaf(kv.x, qv.x, s);
                s = fmaf(kv.y, qv.y, s);
                s = fmaf(kv.z, qv.z, s);
                s = fmaf(kv.w, qv.w, s);
            }
#pragma unroll
            for (int off = 16; off; off >>= 1)
                s += __shfl_xor_sync(0xffffffffu, s, off);
            if (lane == 0) sc[row][k] = s * 0.044194173824159216f;  // 1/sqrt(512)
        }
    }
    __syncthreads();

    // Softmax: warp 0 -> row 0, warp 1 -> row 1
    if (warp < 2) {
        float s = sc[warp][lane];
        float m = s;
#pragma unroll
        for (int off = 16; off; off >>= 1)
            m = fmaxf(m, __shfl_xor_sync(0xffffffffu, m, off));
        float p = __expf(s - m);
        float sum = p;
#pragma unroll
        for (int off = 16; off; off >>= 1)
            sum += __shfl_xor_sync(0xffffffffu, sum, off);
        attn_s[warp][lane] = p / sum;
    }
    __syncthreads();

    // Combine + blend: thread -> row = tid>>7, float4 dim = tid&127
    {
        const int row = tid >> 7, d4 = tid & 127;
        const int b = b0 + row;
        const float4* V4 = (const float4*)values;
        const size_t vbase = (size_t)b * K_SZ * 128;
        float4 acc = make_float4(0.f, 0.f, 0.f, 0.f);
#pragma unroll
        for (int k = 0; k < K_SZ; k++) {
            const float a = attn_s[row][k];
            float4 v = V4[vbase + (size_t)k * 128 + d4];
            acc.x = fmaf(a, v.x, acc.x);
            acc.y = fmaf(a, v.y, acc.y);
            acc.z = fmaf(a, v.z, acc.z);
            acc.w = fmaf(a, v.w, acc.w);
        }
        float4 xv = ((const float4*)x)[(size_t)b * 128 + d4];
        float4 o;
        o.x = 0.5f * xv.x + 0.5f * acc.x;
        o.y = 0.5f * xv.y + 0.5f * acc.y;
        o.z = 0.5f * xv.z + 0.5f * acc.z;
        o.w = 0.5f * xv.w + 0.5f * acc.w;
        ((float4*)out)[(size_t)b * 128 + d4] = o;
    }
}

// ---------------------------------------------------------------------------
extern "C" void kernel_launch(void* const* d_in, const int* in_sizes, int n_in,
                              void* d_out, int out_size) {
    (void)in_sizes; (void)n_in; (void)out_size;
    const float* x      = (const float*)d_in[0];
    const float* keys   = (const float*)d_in[1];
    const float* values = (const float*)d_in[2];
    const float* w1     = (const float*)d_in[3];
    const float* b1     = (const float*)d_in[4];
    const float* w2     = (const float*)d_in[5];
    // d_in[6] = b2: per-row constant in scores -> cancels in softmax.
    float* out = (float*)d_out;

    static cudaStream_t s2 = nullptr;
    static cudaEvent_t evRoot = nullptr, evSplit = nullptr, evPart = nullptr,
                       evG2 = nullptr, evJoin = nullptr;
    if (!s2) {
        cudaStreamCreateWithFlags(&s2, cudaStreamNonBlocking);
        cudaEventCreateWithFlags(&evRoot, cudaEventDisableTiming);
        cudaEventCreateWithFlags(&evSplit, cudaEventDisableTiming);
        cudaEventCreateWithFlags(&evPart, cudaEventDisableTiming);
        cudaEventCreateWithFlags(&evG2, cudaEventDisableTiming);
        cudaEventCreateWithFlags(&evJoin, cudaEventDisableTiming);
    }

    const int gemm_smem = 9 * SA_HALVES * (int)sizeof(__nv_bfloat16);  // 92160
    cudaFuncSetAttribute(gemm_mma_kernel,
                         cudaFuncAttributeMaxDynamicSharedMemorySize, gemm_smem);

    // Fork s2 off the main (captured) stream.
    cudaEventRecord(evRoot, 0);
    cudaStreamWaitEvent(s2, evRoot, 0);

    // s2: split_x (independent of the M-chain)
    split_x_kernel<<<4096, 256, 0, s2>>>(x, b1, w2);
    cudaEventRecord(evSplit, s2);

    // main: M-chain
    compute_M_part_kernel<<<dim3(8, 8, 8), 256>>>(w1, w2);
    reduce_split_kernel<<<256, 256>>>();

    // main: split-K lead chunk (rows 0..2047, 4 k-slices -> partials)
    cudaStreamWaitEvent(0, evSplit, 0);
    gemm_mma_kernel<<<dim3(4, 16, 4), 256, gemm_smem>>>(0, 1);
    cudaEventRecord(evPart, 0);

    // main: bulk gemm (rows 2048..8191, full k, bias)
    gemm_mma_kernel<<<dim3(4, 48), 256, gemm_smem>>>(16, 0);
    cudaEventRecord(evG2, 0);

    // s2: attention chunks (2 rows/CTA); lead chunk sums partials itself
    cudaStreamWaitEvent(s2, evPart, 0);
    attn_kernel<<<Q1ROWS / 2, 256, 0, s2>>>(x, keys, values, out, 0, 1);
    cudaStreamWaitEvent(s2, evG2, 0);
    attn_kernel<<<(B_SZ - Q1ROWS) / 2, 256, 0, s2>>>(x, keys, values, out, Q1ROWS, 0);

    // Join s2 back into the captured stream.
    cudaEventRecord(evJoin, s2);
    cudaStreamWaitEvent(0, evJoin, 0);
}

// round 15
// speedup vs baseline: 1.1078x; 1.0233x over previous
#include <cuda_runtime.h>
#include <cuda_bf16.h>
#include <cstdint>

// Problem constants
#define B_SZ 8192
#define K_SZ 32
#define D_SZ 512
#define KA   1024            // A cols: [xh | xl] ; Bop K-range: [Mh ; Ml]
#define ASTRIDE 40           // smem row stride in bf16 halves (conflict-free ldmatrix)
#define SA_HALVES (128 * ASTRIDE)
#define NPART 8              // split-K factor for compute_M
#define Q1ROWS 2048          // rows computed by the split-K lead chunk

// Scratch (device globals — no allocation allowed)
__device__ float4 g_q2[B_SZ * (D_SZ / 4)];            // 16 MB: q2 = x@M + c
__device__ float  g_c[D_SZ];                          // c = b1 @ w2
__device__ __nv_bfloat16 g_A2[B_SZ * KA];             // 16 MB: [xh | xl]
__device__ __nv_bfloat16 g_Bop[D_SZ * KA];            // 1 MB:  Bop[n][k] = [Mh;Ml] K-major
__device__ float g_MpartT[NPART][D_SZ * D_SZ];        // 8 MB:  partial M, transposed
__device__ float g_qpart[4][Q1ROWS * D_SZ];           // 16 MB: split-K partials, rows 0..2047

__device__ __forceinline__ uint32_t smem_u32(const void* p) {
    uint32_t a;
    asm("{ .reg .u64 t; cvta.to.shared.u64 t, %1; cvt.u32.u64 %0, t; }" : "=r"(a) : "l"(p));
    return a;
}

// ---------------------------------------------------------------------------
// Kernel 1a: split-K partial of M: part[z][n][d] = sum_{e in slice z} w1[e,d]w2[e,n]
// ---------------------------------------------------------------------------
__global__ void compute_M_part_kernel(const float* __restrict__ w1,
                                      const float* __restrict__ w2) {
    __shared__ float As[16][64];
    __shared__ float Bs[16][64];
    const int tid = threadIdx.x;
    const int lRow = tid / 16;
    const int lCol = (tid % 16) * 4;
    const int d0 = blockIdx.y * 64;
    const int j0 = blockIdx.x * 64;
    const int e_lo = blockIdx.z * 64;
    const int tRow = (tid / 16) * 4;
    const int tCol = (tid % 16) * 4;

    float acc[4][4] = {};
    for (int e0 = e_lo; e0 < e_lo + 64; e0 += 16) {
        *(float4*)&As[lRow][lCol] = *(const float4*)(w1 + (e0 + lRow) * D_SZ + d0 + lCol);
        *(float4*)&Bs[lRow][lCol] = *(const float4*)(w2 + (e0 + lRow) * D_SZ + j0 + lCol);
        __syncthreads();
#pragma unroll
        for (int e = 0; e < 16; e++) {
            float rm[4], rn[4];
#pragma unroll
            for (int i = 0; i < 4; i++) rm[i] = As[e][tRow + i];
#pragma unroll
            for (int j = 0; j < 4; j++) rn[j] = Bs[e][tCol + j];
#pragma unroll
            for (int i = 0; i < 4; i++)
#pragma unroll
                for (int j = 0; j < 4; j++)
                    acc[i][j] = fmaf(rm[i], rn[j], acc[i][j]);
        }
        __syncthreads();
    }
    float* part = g_MpartT[blockIdx.z];
#pragma unroll
    for (int jj = 0; jj < 4; jj++) {
        const int n = j0 + tCol + jj;
        float4 v = make_float4(acc[0][jj], acc[1][jj], acc[2][jj], acc[3][jj]);
        *(float4*)(part + (size_t)n * D_SZ + d0 + tRow) = v;
    }
}

// ---------------------------------------------------------------------------
// Kernel 1b: reduce partials, split hi/lo, write g_Bop.
// ---------------------------------------------------------------------------
__global__ void reduce_split_kernel() {
    const int idx = blockIdx.x * blockDim.x + threadIdx.x;  // 65536
    const int n = idx >> 7;
    const int d0 = (idx & 127) * 4;
    float4 s = make_float4(0.f, 0.f, 0.f, 0.f);
#pragma unroll
    for (int p = 0; p < NPART; p++) {
        float4 v = *(const float4*)(g_MpartT[p] + (size_t)n * D_SZ + d0);
        s.x += v.x; s.y += v.y; s.z += v.z; s.w += v.w;
    }
    __nv_bfloat16 h4[4], l4[4];
    const float sv[4] = {s.x, s.y, s.z, s.w};
#pragma unroll
    for (int i = 0; i < 4; i++) {
        __nv_bfloat16 h = __float2bfloat16_rn(sv[i]);
        h4[i] = h;
        l4[i] = __float2bfloat16_rn(sv[i] - __bfloat162float(h));
    }
    *(uint2*)(g_Bop + (size_t)n * KA + d0) = *(uint2*)h4;
    *(uint2*)(g_Bop + (size_t)n * KA + 512 + d0) = *(uint2*)l4;
}

// ---------------------------------------------------------------------------
// Kernel 2: split x -> A2 = [xh | xl]; first 8 CTAs also compute c = b1@w2.
// ---------------------------------------------------------------------------
__global__ void split_x_kernel(const float* __restrict__ x,
                               const float* __restrict__ b1,
                               const float* __restrict__ w2) {
    __shared__ float red[256];
    const int t = blockIdx.x * blockDim.x + threadIdx.x;
    const int b = t >> 7;
    const int c4 = (t & 127) * 4;
    float4 v = *(const float4*)(x + (size_t)b * D_SZ + c4);
    __nv_bfloat16 hx = __float2bfloat16_rn(v.x), hy = __float2bfloat16_rn(v.y);
    __nv_bfloat16 hz = __float2bfloat16_rn(v.z), hw = __float2bfloat16_rn(v.w);
    __nv_bfloat16 lx = __float2bfloat16_rn(v.x - __bfloat162float(hx));
    __nv_bfloat16 ly = __float2bfloat16_rn(v.y - __bfloat162float(hy));
    __nv_bfloat16 lz = __float2bfloat16_rn(v.z - __bfloat162float(hz));
    __nv_bfloat16 lw = __float2bfloat16_rn(v.w - __bfloat162float(hw));
    __nv_bfloat16* row = g_A2 + (size_t)b * KA;
    uint2 hi, lo;
    ((__nv_bfloat16*)&hi)[0] = hx; ((__nv_bfloat16*)&hi)[1] = hy;
    ((__nv_bfloat16*)&hi)[2] = hz; ((__nv_bfloat16*)&hi)[3] = hw;
    ((__nv_bfloat16*)&lo)[0] = lx; ((__nv_bfloat16*)&lo)[1] = ly;
    ((__nv_bfloat16*)&lo)[2] = lz; ((__nv_bfloat16*)&lo)[3] = lw;
    *(uint2*)(row + c4)       = hi;
    *(uint2*)(row + 512 + c4) = lo;

    if (blockIdx.x < 8) {
        const int tid = threadIdx.x;
        const int j = blockIdx.x * 64 + (tid & 63);
        const int eg = tid >> 6;
        float s = 0.f;
        for (int e = eg * 128; e < eg * 128 + 128; e++)
            s = fmaf(b1[e], w2[e * D_SZ + j], s);
        red[tid] = s;
        __syncthreads();
        if (eg == 0)
            g_c[j] = red[tid] + red[tid + 64] + red[tid + 128] + red[tid + 192];
    }
}

// ---------------------------------------------------------------------------
// Kernel 3: warp-MMA bf16 GEMM: q2 = xh@Mh + xh@Ml + xl@Mh (+ c if !kspl)
// R6-benched mainloop. kspl=1: blockIdx.z selects k-slice [z*8, z*8+8),
// raw partials -> g_qpart[z]. kspl=0: full k, bias added, -> g_q2.
// ---------------------------------------------------------------------------
__global__ void __launch_bounds__(256, 2)
gemm_mma_kernel(int m_off, int kspl) {
    extern __shared__ __nv_bfloat16 ds[];
    __nv_bfloat16* sA  = ds;
    __nv_bfloat16* sBh = ds + 3 * SA_HALVES;
    __nv_bfloat16* sBl = ds + 6 * SA_HALVES;

    const int tid = threadIdx.x;
    const int lane = tid & 31;
    const int wid = tid >> 5;
    const int m0 = (blockIdx.y + m_off) * 128;
    const int n0 = blockIdx.x * 128;
    const int mbase = (wid & 3) * 32;
    const int nbase = (wid >> 2) * 64;

    int cBeg = 0, cEnd = 32;
    float* dst = (float*)g_q2;
    if (kspl) {
        const int z = blockIdx.z;
        cBeg = z * 8;
        cEnd = cBeg + 8;
        dst = g_qpart[z];
    }

    const __nv_bfloat16* Ab = g_A2 + (size_t)m0 * KA;
    const __nv_bfloat16* Bb = g_Bop + (size_t)n0 * KA;

    const int lrow0 = tid >> 2;
    const int lcc = (tid & 3) * 8;

    const int aRow = mbase + (lane & 15);
    const int aCol = (lane >= 16) ? 8 : 0;
    const int bRow = nbase + ((lane >= 16) ? 8 : 0) + (lane & 7);
    const int bCol = ((lane >> 3) & 1) * 8;

    float acc[2][8][4];
#pragma unroll
    for (int mf = 0; mf < 2; mf++)
#pragma unroll
        for (int nf = 0; nf < 8; nf++)
#pragma unroll
            for (int r = 0; r < 4; r++) acc[mf][nf][r] = 0.f;

#define LOAD_STAGE(buf, c)                                                          \
    do {                                                                            \
        if ((c) < cEnd) {                                                           \
            const int kb = ((c) & 15) * 32;                                         \
            _Pragma("unroll")                                                       \
            for (int i = 0; i < 2; i++) {                                           \
                int row = lrow0 + i * 64;                                           \
                uint32_t da = smem_u32(&sA[(buf) * SA_HALVES + row * ASTRIDE + lcc]); \
                const void* pa = Ab + (size_t)row * KA + (c) * 32 + lcc;            \
                asm volatile("cp.async.cg.shared.global [%0], [%1], 16;"            \
                             :: "r"(da), "l"(pa) : "memory");                       \
                uint32_t dh = smem_u32(&sBh[(buf) * SA_HALVES + row * ASTRIDE + lcc]); \
                const void* ph = Bb + (size_t)row * KA + kb + lcc;                  \
                asm volatile("cp.async.cg.shared.global [%0], [%1], 16;"            \
                             :: "r"(dh), "l"(ph) : "memory");                       \
                if ((c) < 16) {                                                     \
                    uint32_t dl = smem_u32(&sBl[(buf) * SA_HALVES + row * ASTRIDE + lcc]); \
                    const void* pl = Bb + (size_t)row * KA + 512 + kb + lcc;        \
                    asm volatile("cp.async.cg.shared.global [%0], [%1], 16;"        \
                                 :: "r"(dl), "l"(pl) : "memory");                   \
                }                                                                   \
            }                                                                       \
        }                                                                           \
        asm volatile("cp.async.commit_group;" ::: "memory");                        \
    } while (0)

    LOAD_STAGE(0, cBeg);
    LOAD_STAGE(1, cBeg + 1);

    int buf = 0, nbuf2 = 2;
    for (int c = cBeg; c < cEnd; ++c) {
        LOAD_STAGE(nbuf2, c + 2);
        asm volatile("cp.async.wait_group 2;" ::: "memory");
        __syncthreads();

#pragma unroll
        for (int kf = 0; kf < 2; kf++) {
            uint32_t a[2][4];
#pragma unroll
            for (int mf = 0; mf < 2; mf++) {
                uint32_t addr = smem_u32(
                    &sA[buf * SA_HALVES + (aRow + mf * 16) * ASTRIDE + kf * 16 + aCol]);
                asm volatile(
                    "ldmatrix.sync.aligned.m8n8.x4.shared.b16 {%0,%1,%2,%3}, [%4];"
                    : "=r"(a[mf][0]), "=r"(a[mf][1]), "=r"(a[mf][2]), "=r"(a[mf][3])
                    : "r"(addr));
            }
            uint32_t b[4][4];
#pragma unroll
            for (int np = 0; np < 4; np++) {
                uint32_t addr = smem_u32(
                    &sBh[buf * SA_HALVES + (bRow + np * 16) * ASTRIDE + kf * 16 + bCol]);
                asm volatile(
                    "ldmatrix.sync.aligned.m8n8.x4.shared.b16 {%0,%1,%2,%3}, [%4];"
                    : "=r"(b[np][0]), "=r"(b[np][1]), "=r"(b[np][2]), "=r"(b[np][3])
                    : "r"(addr));
            }
#pragma unroll
            for (int mf = 0; mf < 2; mf++)
#pragma unroll
                for (int nf = 0; nf < 8; nf++) {
                    asm volatile(
                        "mma.sync.aligned.m16n8k16.row.col.f32.bf16.bf16.f32 "
                        "{%0,%1,%2,%3}, {%4,%5,%6,%7}, {%8,%9}, {%0,%1,%2,%3};"
                        : "+f"(acc[mf][nf][0]), "+f"(acc[mf][nf][1]),
                          "+f"(acc[mf][nf][2]), "+f"(acc[mf][nf][3])
                        : "r"(a[mf][0]), "r"(a[mf][1]), "r"(a[mf][2]), "r"(a[mf][3]),
                          "r"(b[nf >> 1][(nf & 1) * 2]), "r"(b[nf >> 1][(nf & 1) * 2 + 1]));
                }
            if (c < 16) {
#pragma unroll
                for (int np = 0; np < 4; np++) {
                    uint32_t addr = smem_u32(
                        &sBl[buf * SA_HALVES + (bRow + np * 16) * ASTRIDE + kf * 16 + bCol]);
                    asm volatile(
                        "ldmatrix.sync.aligned.m8n8.x4.shared.b16 {%0,%1,%2,%3}, [%4];"
                        : "=r"(b[np][0]), "=r"(b[np][1]), "=r"(b[np][2]), "=r"(b[np][3])
                        : "r"(addr));
                }
#pragma unroll
                for (int mf = 0; mf < 2; mf++)
#pragma unroll
                    for (int nf = 0; nf < 8; nf++) {
                        asm volatile(
                            "mma.sync.aligned.m16n8k16.row.col.f32.bf16.bf16.f32 "
                            "{%0,%1,%2,%3}, {%4,%5,%6,%7}, {%8,%9}, {%0,%1,%2,%3};"
                            : "+f"(acc[mf][nf][0]), "+f"(acc[mf][nf][1]),
                              "+f"(acc[mf][nf][2]), "+f"(acc[mf][nf][3])
                            : "r"(a[mf][0]), "r"(a[mf][1]), "r"(a[mf][2]), "r"(a[mf][3]),
                              "r"(b[nf >> 1][(nf & 1) * 2]), "r"(b[nf >> 1][(nf & 1) * 2 + 1]));
                    }
            }
        }
        __syncthreads();
        buf = (buf == 2) ? 0 : buf + 1;
        nbuf2 = (nbuf2 == 2) ? 0 : nbuf2 + 1;
    }

    // Epilogue (bias only for the full-k path)
    const float bmul = kspl ? 0.f : 1.f;
    const int g = lane >> 2;
    const int t4 = lane & 3;
#pragma unroll
    for (int mf = 0; mf < 2; mf++) {
#pragma unroll
        for (int nf = 0; nf < 8; nf++) {
            const int col = n0 + nbase + nf * 8 + t4 * 2;
            const float c0 = g_c[col] * bmul, c1 = g_c[col + 1] * bmul;
            const int r0 = m0 + mbase + mf * 16 + g;
            float2 v0 = make_float2(acc[mf][nf][0] + c0, acc[mf][nf][1] + c1);
            float2 v1 = make_float2(acc[mf][nf][2] + c0, acc[mf][nf][3] + c1);
            *(float2*)(dst + (size_t)r0 * D_SZ + col) = v0;
            *(float2*)(dst + (size_t)(r0 + 8) * D_SZ + col) = v1;
        }
    }
}

// ---------------------------------------------------------------------------
// Kernel 4: attention — R11 body (1 row/CTA, float2 values, 88.7% HBM).
// use_part=1: q2 row = sum of 4 k-slice partials + bias (lead rows).
// ---------------------------------------------------------------------------
__global__ void __launch_bounds__(256)
attn_kernel(const float* __restrict__ x,
            const float* __restrict__ keys,
            const float* __restrict__ values,
            float* __restrict__ out, int b_off, int use_part) {
    const int b = blockIdx.x + b_off;
    const int tid = threadIdx.x;
    const int lane = tid & 31;
    const int warp = tid >> 5;

    __shared__ float4 q2s[128];
    __shared__ float sc[32];
    __shared__ float attn_s[32];

    if (tid < 128) {
        const size_t gq = (size_t)b * 128 + tid;
        float4 q;
        if (use_part) {
            float4 p0 = ((const float4*)g_qpart[0])[gq];
            float4 p1 = ((const float4*)g_qpart[1])[gq];
            float4 p2 = ((const float4*)g_qpart[2])[gq];
            float4 p3 = ((const float4*)g_qpart[3])[gq];
            float4 cb = ((const float4*)g_c)[tid];
            q = make_float4(p0.x + p1.x + p2.x + p3.x + cb.x,
                            p0.y + p1.y + p2.y + p3.y + cb.y,
                            p0.z + p1.z + p2.z + p3.z + cb.z,
                            p0.w + p1.w + p2.w + p3.w + cb.w);
        } else {
            q = g_q2[gq];
        }
        q2s[tid] = q;
    }
    __syncthreads();

    const float4* K4 = (const float4*)keys;
#pragma unroll
    for (int kk = 0; kk < 4; kk++) {
        const int k = warp * 4 + kk;
        const long base = ((long)b * K_SZ + k) * 128;
        float s = 0.f;
#pragma unroll
        for (int i = 0; i < 4; i++) {
            float4 kv = K4[base + i * 32 + lane];
            float4 qv = q2s[i * 32 + lane];
            s = fmaf(kv.x, qv.x, s);
            s = fmaf(kv.y, qv.y, s);
            s = fmaf(kv.z, qv.z, s);
            s = fmaf(kv.w, qv.w, s);
        }
#pragma unroll
        for (int off = 16; off; off >>= 1)
            s += __shfl_xor_sync(0xffffffffu, s, off);
        if (lane == 0) sc[k] = s * 0.044194173824159216f;  // 1/sqrt(512)
    }
    __syncthreads();

    if (tid < 32) {
        float s = sc[tid];
        float m = s;
#pragma unroll
        for (int off = 16; off; off >>= 1)
            m = fmaxf(m, __shfl_xor_sync(0xffffffffu, m, off));
        float p = __expf(s - m);
        float sum = p;
#pragma unroll
        for (int off = 16; off; off >>= 1)
            sum += __shfl_xor_sync(0xffffffffu, sum, off);
        attn_s[tid] = p / sum;
    }
    __syncthreads();

    const float2* V2 = (const float2*)values;
    const float2* X2 = (const float2*)x;
    float2 acc = make_float2(0.f, 0.f);
    const long vbase = (long)b * K_SZ * 256;
#pragma unroll
    for (int k = 0; k < K_SZ; k++) {
        const float a = attn_s[k];
        float2 v = V2[vbase + k * 256 + tid];
        acc.x = fmaf(a, v.x, acc.x);
        acc.y = fmaf(a, v.y, acc.y);
    }
    float2 xv = X2[(long)b * 256 + tid];
    float2 o;
    o.x = 0.5f * xv.x + 0.5f * acc.x;
    o.y = 0.5f * xv.y + 0.5f * acc.y;
    ((float2*)out)[(long)b * 256 + tid] = o;
}

// ---------------------------------------------------------------------------
extern "C" void kernel_launch(void* const* d_in, const int* in_sizes, int n_in,
                              void* d_out, int out_size) {
    (void)in_sizes; (void)n_in; (void)out_size;
    const float* x      = (const float*)d_in[0];
    const float* keys   = (const float*)d_in[1];
    const float* values = (const float*)d_in[2];
    const float* w1     = (const float*)d_in[3];
    const float* b1     = (const float*)d_in[4];
    const float* w2     = (const float*)d_in[5];
    // d_in[6] = b2: per-row constant in scores -> cancels in softmax.
    float* out = (float*)d_out;

    static cudaStream_t s2 = nullptr;
    static cudaEvent_t evRoot = nullptr, evSplit = nullptr, evPart = nullptr,
                       evG2 = nullptr, evJoin = nullptr;
    if (!s2) {
        cudaStreamCreateWithFlags(&s2, cudaStreamNonBlocking);
        cudaEventCreateWithFlags(&evRoot, cudaEventDisableTiming);
        cudaEventCreateWithFlags(&evSplit, cudaEventDisableTiming);
        cudaEventCreateWithFlags(&evPart, cudaEventDisableTiming);
        cudaEventCreateWithFlags(&evG2, cudaEventDisableTiming);
        cudaEventCreateWithFlags(&evJoin, cudaEventDisableTiming);
    }

    const int gemm_smem = 9 * SA_HALVES * (int)sizeof(__nv_bfloat16);  // 92160
    cudaFuncSetAttribute(gemm_mma_kernel,
                         cudaFuncAttributeMaxDynamicSharedMemorySize, gemm_smem);

    // Fork s2 off the main (captured) stream.
    cudaEventRecord(evRoot, 0);
    cudaStreamWaitEvent(s2, evRoot, 0);

    // s2: split_x (independent of the M-chain)
    split_x_kernel<<<4096, 256, 0, s2>>>(x, b1, w2);
    cudaEventRecord(evSplit, s2);

    // main: M-chain
    compute_M_part_kernel<<<dim3(8, 8, 8), 256>>>(w1, w2);
    reduce_split_kernel<<<256, 256>>>();

    // main: split-K lead chunk (rows 0..2047, 4 k-slices -> partials)
    cudaStreamWaitEvent(0, evSplit, 0);
    gemm_mma_kernel<<<dim3(4, 16, 4), 256, gemm_smem>>>(0, 1);
    cudaEventRecord(evPart, 0);

    // main: bulk gemm (rows 2048..8191, full k, bias)
    gemm_mma_kernel<<<dim3(4, 48), 256, gemm_smem>>>(16, 0);
    cudaEventRecord(evG2, 0);

    // s2: attention chunks; lead chunk sums the partials itself (no reduce launch)
    cudaStreamWaitEvent(s2, evPart, 0);
    attn_kernel<<<Q1ROWS, 256, 0, s2>>>(x, keys, values, out, 0, 1);
    cudaStreamWaitEvent(s2, evG2, 0);
    attn_kernel<<<B_SZ - Q1ROWS, 256, 0, s2>>>(x, keys, values, out, Q1ROWS, 0);

    // Join s2 back into the captured stream.
    cudaEventRecord(evJoin, s2);
    cudaStreamWaitEvent(0, evJoin, 0);
}